// round 1
// baseline (speedup 1.0000x reference)
#include <cuda_runtime.h>
#include <cuda_bf16.h>

#define IN_F   4096
#define OUT_F  4096
#define BATCH  128
#define NNZ_MAX 1600000

// ---------------- device scratch (no allocations allowed) ----------------
__device__ float g_inpT[IN_F * BATCH];          // 2 MB: input transposed, columns contiguous
__device__ float g_svals[NNZ_MAX];              // 6.4 MB: values sorted by row
__device__ int   g_scols[NNZ_MAX];              // 6.4 MB: cols sorted by row
__device__ int   g_cnt[OUT_F];                  // per-row nnz count
__device__ int   g_rowstart[OUT_F + 1];         // CSR row pointers
__device__ int   g_cursor[OUT_F];               // scatter cursors

// ---------------- kernel 1: zero counters ----------------
__global__ void k_zero_cnt() {
    int i = blockIdx.x * blockDim.x + threadIdx.x;
    if (i < OUT_F) g_cnt[i] = 0;
}

// ---------------- kernel 2: tiled transpose inp[B,IN_F] -> inpT[IN_F,B] ----------------
__global__ void k_transpose(const float* __restrict__ inp) {
    __shared__ float tile[32][33];
    int c0 = blockIdx.x * 32;   // column block in IN_F
    int b0 = blockIdx.y * 32;   // row block in BATCH
    int tx = threadIdx.x, ty = threadIdx.y;
    // read coalesced from inp
    tile[ty][tx] = inp[(b0 + ty) * IN_F + (c0 + tx)];
    __syncthreads();
    // write coalesced to inpT
    g_inpT[(c0 + ty) * BATCH + (b0 + tx)] = tile[tx][ty];
}

// ---------------- kernel 3: row histogram (SMEM-aggregated) ----------------
__global__ void k_count(const int* __restrict__ rows, int n) {
    __shared__ int h[OUT_F];
    for (int i = threadIdx.x; i < OUT_F; i += blockDim.x) h[i] = 0;
    __syncthreads();
    int stride = gridDim.x * blockDim.x;
    for (int i = blockIdx.x * blockDim.x + threadIdx.x; i < n; i += stride)
        atomicAdd(&h[rows[i]], 1);
    __syncthreads();
    for (int i = threadIdx.x; i < OUT_F; i += blockDim.x)
        if (h[i]) atomicAdd(&g_cnt[i], h[i]);
}

// ---------------- kernel 4: exclusive scan of 4096 counts (single CTA) ----------------
__global__ void k_scan(int n) {
    __shared__ int s[1024];
    int t = threadIdx.x;                 // 1024 threads, 4 rows each
    int v0 = g_cnt[t * 4 + 0];
    int v1 = g_cnt[t * 4 + 1];
    int v2 = g_cnt[t * 4 + 2];
    int v3 = g_cnt[t * 4 + 3];
    int sum = v0 + v1 + v2 + v3;
    s[t] = sum;
    __syncthreads();
    // Hillis-Steele inclusive scan over 1024 partials
    for (int off = 1; off < 1024; off <<= 1) {
        int x = (t >= off) ? s[t - off] : 0;
        __syncthreads();
        s[t] += x;
        __syncthreads();
    }
    int excl = s[t] - sum;
    int r0 = excl;
    int r1 = r0 + v0;
    int r2 = r1 + v1;
    int r3 = r2 + v2;
    g_rowstart[t * 4 + 0] = r0;  g_cursor[t * 4 + 0] = r0;
    g_rowstart[t * 4 + 1] = r1;  g_cursor[t * 4 + 1] = r1;
    g_rowstart[t * 4 + 2] = r2;  g_cursor[t * 4 + 2] = r2;
    g_rowstart[t * 4 + 3] = r3;  g_cursor[t * 4 + 3] = r3;
    if (t == 1023) g_rowstart[OUT_F] = n;
}

// ---------------- kernel 5: scatter (col,val) into row-sorted order ----------------
__global__ void k_scatter(const int* __restrict__ rows,
                          const int* __restrict__ cols,
                          const float* __restrict__ vals, int n) {
    int stride = gridDim.x * blockDim.x;
    for (int i = blockIdx.x * blockDim.x + threadIdx.x; i < n; i += stride) {
        int r = rows[i];
        int pos = atomicAdd(&g_cursor[r], 1);
        g_scols[pos] = cols[i];
        g_svals[pos] = vals[i];
    }
}

// ---------------- kernel 6: per-row accumulation ----------------
// block = one output row r; 128 threads = 128 batch lanes.
__global__ void __launch_bounds__(128) k_compute(const float* __restrict__ bias,
                                                 float* __restrict__ out) {
    __shared__ int   scol[128];
    __shared__ float sval[128];
    int r = blockIdx.x;
    int b = threadIdx.x;
    int s = g_rowstart[r];
    int e = g_rowstart[r + 1];
    float acc0 = 0.f, acc1 = 0.f;
    for (int base = s; base < e; base += 128) {
        int j = base + b;
        if (j < e) {
            scol[b] = g_scols[j];
            sval[b] = g_svals[j];
        }
        __syncthreads();
        int cnt = min(128, e - base);
        int k = 0;
        #pragma unroll 4
        for (; k + 1 < cnt; k += 2) {
            acc0 = fmaf(sval[k],     g_inpT[scol[k]     * BATCH + b], acc0);
            acc1 = fmaf(sval[k + 1], g_inpT[scol[k + 1] * BATCH + b], acc1);
        }
        if (k < cnt)
            acc0 = fmaf(sval[k], g_inpT[scol[k] * BATCH + b], acc0);
        __syncthreads();
    }
    out[b * OUT_F + r] = acc0 + acc1 + bias[r];
}

// ---------------- launch ----------------
extern "C" void kernel_launch(void* const* d_in, const int* in_sizes, int n_in,
                              void* d_out, int out_size) {
    const float* inp    = (const float*)d_in[0];   // [B, IN_F]
    const float* w_vals = (const float*)d_in[1];   // [nnz]
    const int*   w_rows = (const int*)  d_in[2];   // [nnz]
    const int*   w_cols = (const int*)  d_in[3];   // [nnz]
    const float* bias   = (const float*)d_in[4];   // [OUT_F]
    float*       out    = (float*)d_out;           // [B, OUT_F]
    int n = in_sizes[1];

    k_zero_cnt<<<(OUT_F + 255) / 256, 256>>>();
    k_transpose<<<dim3(IN_F / 32, BATCH / 32), dim3(32, 32)>>>(inp);
    k_count<<<256, 256>>>(w_rows, n);
    k_scan<<<1, 1024>>>(n);
    k_scatter<<<512, 256>>>(w_rows, w_cols, w_vals, n);
    k_compute<<<OUT_F, 128>>>(bias, out);
}

// round 5
// speedup vs baseline: 1.7197x; 1.7197x over previous
#include <cuda_runtime.h>
#include <cuda_bf16.h>
#include <cstdint>

#define IN_F   4096
#define OUT_F  4096
#define BATCH  128
#define KSPLIT 4
#define KC     (IN_F / KSPLIT)     // 1024 K per CTA
#define CK     32                  // K per chunk
#define NCHUNK (KC / CK)           // 32
#define TSTRIDE 80                 // smem tile row stride (bytes): 64B data + 16B pad
#define TILE_B  (128 * TSTRIDE)    // 10240 B per 128x32 bf16 tile
#define STAGE_B (4 * TILE_B)       // Ah, Al, Bh, Bl
#define SMEM_TOTAL (2 * STAGE_B)   // 81920 B double-buffered

// ===================== device scratch =====================
__device__ __align__(16) float g_W[(size_t)OUT_F * IN_F];              // 64 MB dense W (zero invariant)
__device__ __align__(16) float g_part[(size_t)KSPLIT * BATCH * OUT_F]; // 8 MB K-split partials

// ===================== helpers =====================
__device__ __forceinline__ uint32_t smem_u32(const void* p) {
    uint32_t a;
    asm("{ .reg .u64 t; cvta.to.shared.u64 t, %1; cvt.u32.u64 %0, t; }" : "=r"(a) : "l"(p));
    return a;
}
__device__ __forceinline__ void ldsm4(uint32_t* r, uint32_t addr) {
    asm volatile("ldmatrix.sync.aligned.m8n8.x4.shared.b16 {%0,%1,%2,%3}, [%4];"
                 : "=r"(r[0]), "=r"(r[1]), "=r"(r[2]), "=r"(r[3]) : "r"(addr));
}
__device__ __forceinline__ void mma_bf16(float* d, const uint32_t* a, const uint32_t* b) {
    asm volatile(
        "mma.sync.aligned.m16n8k16.row.col.f32.bf16.bf16.f32 "
        "{%0,%1,%2,%3}, {%4,%5,%6,%7}, {%8,%9}, {%0,%1,%2,%3};"
        : "+f"(d[0]), "+f"(d[1]), "+f"(d[2]), "+f"(d[3])
        : "r"(a[0]), "r"(a[1]), "r"(a[2]), "r"(a[3]), "r"(b[0]), "r"(b[1]));
}
#define STS128(r0, r1, r2, r3, a) \
    asm volatile("st.shared.v4.b32 [%0], {%1,%2,%3,%4};" :: "r"(a), "r"(r0), "r"(r1), "r"(r2), "r"(r3) : "memory")

// split two fp32 into packed bf16 hi / bf16 lo (residual)
__device__ __forceinline__ void split2(float x, float y, uint32_t& h, uint32_t& l) {
    __nv_bfloat16 hx = __float2bfloat16(x);
    __nv_bfloat16 hy = __float2bfloat16(y);
    __nv_bfloat16 lx = __float2bfloat16(x - __bfloat162float(hx));
    __nv_bfloat16 ly = __float2bfloat16(y - __bfloat162float(hy));
    h = ((uint32_t)__bfloat16_as_ushort(hy) << 16) | (uint32_t)__bfloat16_as_ushort(hx);
    l = ((uint32_t)__bfloat16_as_ushort(ly) << 16) | (uint32_t)__bfloat16_as_ushort(lx);
}

// ===================== kernel 1: scatter-add COO -> dense W =====================
__global__ void k_scatter(const int* __restrict__ rows, const int* __restrict__ cols,
                          const float* __restrict__ vals, int n) {
    int stride = gridDim.x * blockDim.x;
    for (int i = blockIdx.x * blockDim.x + threadIdx.x; i < n; i += stride)
        atomicAdd(&g_W[(size_t)rows[i] * IN_F + cols[i]], vals[i]);
}

// ===================== kernel 2: split-bf16 GEMM via mma.sync =====================
// grid (32 n-tiles, 4 k-splits), 256 threads. C = A[128,4096] * W^T, K-split partials.
__global__ void __launch_bounds__(256, 1) k_gemm(const float* __restrict__ inp) {
    extern __shared__ char smem[];
    const uint32_t sb = smem_u32(smem);

    const int tid  = threadIdx.x;
    const int wid  = tid >> 5;
    const int lane = tid & 31;
    const int n0   = blockIdx.x * 128;
    const int kbase = blockIdx.y * KC;

    const int wm = (wid >> 2) * 64;   // warp m offset (0 / 64)
    const int wn = (wid & 3) * 32;    // warp n offset (0/32/64/96)

    float acc[4][4][4];
    #pragma unroll
    for (int i = 0; i < 4; i++)
        #pragma unroll
        for (int j = 0; j < 4; j++)
            #pragma unroll
            for (int c = 0; c < 4; c++) acc[i][j][c] = 0.f;

    // global load mapping: 2 threads per row, each covers 16 consecutive floats
    const int r = tid >> 1;       // row 0..127
    const int q = tid & 1;        // half of 32-float chunk row
    const float4* pA = (const float4*)(inp + (size_t)r * IN_F + kbase + q * 16);
    const float4* pB = (const float4*)(g_W + (size_t)(n0 + r) * IN_F + kbase + q * 16);
    float4*       pBz = (float4*)(g_W + (size_t)(n0 + r) * IN_F + kbase + q * 16);

    const uint32_t sts_off = (uint32_t)r * TSTRIDE + q * 32;  // 32B per thread per tile

    float4 fa[4], fb[4];

    // ---- prologue: chunk 0 ----
    #pragma unroll
    for (int i = 0; i < 4; i++) { fa[i] = pA[i]; fb[i] = pB[i]; }
    {
        uint32_t st = sb;  // stage 0
        uint32_t h[8], l[8];
        #pragma unroll
        for (int i = 0; i < 4; i++) { split2(fa[i].x, fa[i].y, h[2*i], l[2*i]); split2(fa[i].z, fa[i].w, h[2*i+1], l[2*i+1]); }
        STS128(h[0], h[1], h[2], h[3], st + sts_off);
        STS128(h[4], h[5], h[6], h[7], st + sts_off + 16);
        STS128(l[0], l[1], l[2], l[3], st + TILE_B + sts_off);
        STS128(l[4], l[5], l[6], l[7], st + TILE_B + sts_off + 16);
        #pragma unroll
        for (int i = 0; i < 4; i++) { split2(fb[i].x, fb[i].y, h[2*i], l[2*i]); split2(fb[i].z, fb[i].w, h[2*i+1], l[2*i+1]); }
        STS128(h[0], h[1], h[2], h[3], st + 2 * TILE_B + sts_off);
        STS128(h[4], h[5], h[6], h[7], st + 2 * TILE_B + sts_off + 16);
        STS128(l[0], l[1], l[2], l[3], st + 3 * TILE_B + sts_off);
        STS128(l[4], l[5], l[6], l[7], st + 3 * TILE_B + sts_off + 16);
        const float4 z4 = make_float4(0.f, 0.f, 0.f, 0.f);
        #pragma unroll
        for (int i = 0; i < 4; i++) pBz[i] = z4;   // restore zero invariant for chunk 0
    }
    __syncthreads();

    // ldmatrix per-lane offsets
    const uint32_t a_off = (uint32_t)(wm + (lane & 15)) * TSTRIDE + (lane >> 4) * 16;
    const uint32_t b_off = (uint32_t)(wn + (lane & 7) + ((lane >> 4) & 1) * 8) * TSTRIDE
                         + ((lane >> 3) & 1) * 16;

    #pragma unroll 1
    for (int c = 0; c < NCHUNK; c++) {
        const bool more = (c + 1 < NCHUNK);
        if (more) {
            #pragma unroll
            for (int i = 0; i < 4; i++) { fa[i] = pA[(c + 1) * 8 + i]; fb[i] = pB[(c + 1) * 8 + i]; }
        }

        // ---- MMA on stage c&1 ----
        {
            const uint32_t st = sb + (uint32_t)(c & 1) * STAGE_B;
            const uint32_t Ah = st, Al = st + TILE_B, Bh = st + 2 * TILE_B, Bl = st + 3 * TILE_B;
            #pragma unroll
            for (int ks = 0; ks < 2; ks++) {
                uint32_t ah[16], al[16], bh[8], bl[8];
                #pragma unroll
                for (int i = 0; i < 4; i++) {
                    ldsm4(ah + 4 * i, Ah + a_off + i * (16 * TSTRIDE) + ks * 32);
                    ldsm4(al + 4 * i, Al + a_off + i * (16 * TSTRIDE) + ks * 32);
                }
                #pragma unroll
                for (int j = 0; j < 2; j++) {
                    ldsm4(bh + 4 * j, Bh + b_off + j * (16 * TSTRIDE) + ks * 32);
                    ldsm4(bl + 4 * j, Bl + b_off + j * (16 * TSTRIDE) + ks * 32);
                }
                #pragma unroll
                for (int i = 0; i < 4; i++) {
                    #pragma unroll
                    for (int jn = 0; jn < 4; jn++) {
                        const uint32_t* bp = bh + (jn >> 1) * 4 + (jn & 1) * 2;
                        const uint32_t* lp = bl + (jn >> 1) * 4 + (jn & 1) * 2;
                        mma_bf16(acc[i][jn], ah + 4 * i, bp);  // Ah*Bh
                        mma_bf16(acc[i][jn], ah + 4 * i, lp);  // Ah*Bl
                        mma_bf16(acc[i][jn], al + 4 * i, bp);  // Al*Bh
                    }
                }
            }
        }
        __syncthreads();

        if (more) {
            const uint32_t st = sb + (uint32_t)((c + 1) & 1) * STAGE_B;
            uint32_t h[8], l[8];
            #pragma unroll
            for (int i = 0; i < 4; i++) { split2(fa[i].x, fa[i].y, h[2*i], l[2*i]); split2(fa[i].z, fa[i].w, h[2*i+1], l[2*i+1]); }
            STS128(h[0], h[1], h[2], h[3], st + sts_off);
            STS128(h[4], h[5], h[6], h[7], st + sts_off + 16);
            STS128(l[0], l[1], l[2], l[3], st + TILE_B + sts_off);
            STS128(l[4], l[5], l[6], l[7], st + TILE_B + sts_off + 16);
            #pragma unroll
            for (int i = 0; i < 4; i++) { split2(fb[i].x, fb[i].y, h[2*i], l[2*i]); split2(fb[i].z, fb[i].w, h[2*i+1], l[2*i+1]); }
            STS128(h[0], h[1], h[2], h[3], st + 2 * TILE_B + sts_off);
            STS128(h[4], h[5], h[6], h[7], st + 2 * TILE_B + sts_off + 16);
            STS128(l[0], l[1], l[2], l[3], st + 3 * TILE_B + sts_off);
            STS128(l[4], l[5], l[6], l[7], st + 3 * TILE_B + sts_off + 16);
            const float4 z4 = make_float4(0.f, 0.f, 0.f, 0.f);
            #pragma unroll
            for (int i = 0; i < 4; i++) pBz[(c + 1) * 8 + i] = z4;  // re-zero W chunk (read exactly once)
            __syncthreads();
        }
    }

    // ---- epilogue: write K-split partials ----
    float* po = g_part + (size_t)blockIdx.y * BATCH * OUT_F + n0;
    #pragma unroll
    for (int i = 0; i < 4; i++) {
        const int m = wm + i * 16 + (lane >> 2);
        #pragma unroll
        for (int jn = 0; jn < 4; jn++) {
            const int n = wn + jn * 8 + (lane & 3) * 2;
            float2 v0 = make_float2(acc[i][jn][0], acc[i][jn][1]);
            float2 v1 = make_float2(acc[i][jn][2], acc[i][jn][3]);
            *(float2*)(po + (size_t)m * OUT_F + n)       = v0;
            *(float2*)(po + (size_t)(m + 8) * OUT_F + n) = v1;
        }
    }
}

// ===================== kernel 3: reduce partials + bias -> out =====================
__global__ void k_reduce(const float* __restrict__ bias, float* __restrict__ out) {
    const int i = blockIdx.x * blockDim.x + threadIdx.x;   // float4 index over [128,4096]
    const size_t stride = (size_t)BATCH * OUT_F / 4;       // 131072
    const float4* p = (const float4*)g_part;
    float4 b  = ((const float4*)bias)[i & 1023];
    float4 v0 = p[i];
    float4 v1 = p[i + stride];
    float4 v2 = p[i + 2 * stride];
    float4 v3 = p[i + 3 * stride];
    float4 s;
    s.x = b.x + v0.x + v1.x + v2.x + v3.x;
    s.y = b.y + v0.y + v1.y + v2.y + v3.y;
    s.z = b.z + v0.z + v1.z + v2.z + v3.z;
    s.w = b.w + v0.w + v1.w + v2.w + v3.w;
    ((float4*)out)[i] = s;
}

// ===================== launch =====================
extern "C" void kernel_launch(void* const* d_in, const int* in_sizes, int n_in,
                              void* d_out, int out_size) {
    const float* inp    = (const float*)d_in[0];   // [B, IN_F]
    const float* w_vals = (const float*)d_in[1];   // [nnz]
    const int*   w_rows = (const int*)  d_in[2];   // [nnz]
    const int*   w_cols = (const int*)  d_in[3];   // [nnz]
    const float* bias   = (const float*)d_in[4];   // [OUT_F]
    float*       out    = (float*)d_out;           // [B, OUT_F]
    const int n = in_sizes[1];

    cudaFuncSetAttribute(k_gemm, cudaFuncAttributeMaxDynamicSharedMemorySize, SMEM_TOTAL);

    k_scatter<<<2048, 256>>>(w_rows, w_cols, w_vals, n);
    k_gemm<<<dim3(32, KSPLIT), 256, SMEM_TOTAL>>>(inp);
    k_reduce<<<(BATCH * OUT_F / 4) / 256, 256>>>(bias, out);
}

// round 6
// speedup vs baseline: 2.0219x; 1.1757x over previous
#include <cuda_runtime.h>
#include <cuda_fp16.h>
#include <cstdint>

#define IN_F   4096
#define OUT_F  4096
#define BATCH  128
#define KSPLIT 4
#define KC     (IN_F / KSPLIT)     // 1024 K per CTA
#define CK     32                  // K per chunk
#define NCHUNK (KC / CK)           // 32
#define TSTRIDE 80                 // smem tile row stride (bytes): 64B data + 16B pad
#define TILE_B  (128 * TSTRIDE)    // 10240 B per 128x32 fp16 tile
#define STAGE_B (2 * TILE_B)       // A, B
#define SMEM_TOTAL (2 * STAGE_B)   // 40960 B double-buffered

// ===================== device scratch =====================
__device__ __align__(16) float g_W[(size_t)OUT_F * IN_F];              // 64 MB dense W (zero invariant)
__device__ __align__(16) float g_part[(size_t)KSPLIT * BATCH * OUT_F]; // 8 MB K-split partials

// ===================== helpers =====================
__device__ __forceinline__ uint32_t smem_u32(const void* p) {
    uint32_t a;
    asm("{ .reg .u64 t; cvta.to.shared.u64 t, %1; cvt.u32.u64 %0, t; }" : "=r"(a) : "l"(p));
    return a;
}
__device__ __forceinline__ void ldsm4(uint32_t* r, uint32_t addr) {
    asm volatile("ldmatrix.sync.aligned.m8n8.x4.shared.b16 {%0,%1,%2,%3}, [%4];"
                 : "=r"(r[0]), "=r"(r[1]), "=r"(r[2]), "=r"(r[3]) : "r"(addr));
}
__device__ __forceinline__ void mma_fp16(float* d, const uint32_t* a, const uint32_t* b) {
    asm volatile(
        "mma.sync.aligned.m16n8k16.row.col.f32.f16.f16.f32 "
        "{%0,%1,%2,%3}, {%4,%5,%6,%7}, {%8,%9}, {%0,%1,%2,%3};"
        : "+f"(d[0]), "+f"(d[1]), "+f"(d[2]), "+f"(d[3])
        : "r"(a[0]), "r"(a[1]), "r"(a[2]), "r"(a[3]), "r"(b[0]), "r"(b[1]));
}
#define STS128(r0, r1, r2, r3, a) \
    asm volatile("st.shared.v4.b32 [%0], {%1,%2,%3,%4};" :: "r"(a), "r"(r0), "r"(r1), "r"(r2), "r"(r3) : "memory")

__device__ __forceinline__ uint32_t pack_h2(float x, float y) {
    __half2 h = __floats2half2_rn(x, y);
    return *reinterpret_cast<uint32_t*>(&h);
}

// ===================== kernel 1: scatter-add COO -> dense W =====================
__global__ void k_scatter(const int* __restrict__ rows, const int* __restrict__ cols,
                          const float* __restrict__ vals, int n) {
    int stride = gridDim.x * blockDim.x;
    for (int i = blockIdx.x * blockDim.x + threadIdx.x; i < n; i += stride)
        atomicAdd(&g_W[(size_t)rows[i] * IN_F + cols[i]], vals[i]);
}

// ===================== kernel 2: fp16 GEMM via mma.sync =====================
// grid (32 n-tiles, 4 k-splits), 256 threads. C = A[128,4096] * W^T, K-split partials.
__global__ void __launch_bounds__(256, 1) k_gemm(const float* __restrict__ inp) {
    extern __shared__ char smem[];
    const uint32_t sb = smem_u32(smem);

    const int tid  = threadIdx.x;
    const int wid  = tid >> 5;
    const int lane = tid & 31;
    const int n0   = blockIdx.x * 128;
    const int kbase = blockIdx.y * KC;

    const int wm = (wid >> 2) * 64;   // warp m offset (0 / 64)
    const int wn = (wid & 3) * 32;    // warp n offset (0/32/64/96)

    float acc[4][4][4];
    #pragma unroll
    for (int i = 0; i < 4; i++)
        #pragma unroll
        for (int j = 0; j < 4; j++)
            #pragma unroll
            for (int c = 0; c < 4; c++) acc[i][j][c] = 0.f;

    // global load mapping: 2 threads per row, each covers 16 consecutive floats
    const int r = tid >> 1;       // row 0..127
    const int q = tid & 1;        // half of 32-float chunk row
    const float4* pA = (const float4*)(inp + (size_t)r * IN_F + kbase + q * 16);
    const float4* pB = (const float4*)(g_W + (size_t)(n0 + r) * IN_F + kbase + q * 16);
    float4*       pBz = (float4*)(g_W + (size_t)(n0 + r) * IN_F + kbase + q * 16);

    const uint32_t sts_off = (uint32_t)r * TSTRIDE + q * 32;  // 32B per thread per tile

    float4 fa[4], fb[4];
    const float4 z4 = make_float4(0.f, 0.f, 0.f, 0.f);

    // ---- prologue: chunk 0 ----
    #pragma unroll
    for (int i = 0; i < 4; i++) { fa[i] = pA[i]; fb[i] = pB[i]; }
    {
        uint32_t st = sb;  // stage 0
        uint32_t h[8];
        #pragma unroll
        for (int i = 0; i < 4; i++) { h[2*i] = pack_h2(fa[i].x, fa[i].y); h[2*i+1] = pack_h2(fa[i].z, fa[i].w); }
        STS128(h[0], h[1], h[2], h[3], st + sts_off);
        STS128(h[4], h[5], h[6], h[7], st + sts_off + 16);
        #pragma unroll
        for (int i = 0; i < 4; i++) { h[2*i] = pack_h2(fb[i].x, fb[i].y); h[2*i+1] = pack_h2(fb[i].z, fb[i].w); }
        STS128(h[0], h[1], h[2], h[3], st + TILE_B + sts_off);
        STS128(h[4], h[5], h[6], h[7], st + TILE_B + sts_off + 16);
        #pragma unroll
        for (int i = 0; i < 4; i++) pBz[i] = z4;   // restore zero invariant for chunk 0
    }
    __syncthreads();

    // ldmatrix per-lane offsets
    const uint32_t a_off = (uint32_t)(wm + (lane & 15)) * TSTRIDE + (lane >> 4) * 16;
    const uint32_t b_off = (uint32_t)(wn + (lane & 7) + ((lane >> 4) & 1) * 8) * TSTRIDE
                         + ((lane >> 3) & 1) * 16;

    #pragma unroll 1
    for (int c = 0; c < NCHUNK; c++) {
        const bool more = (c + 1 < NCHUNK);
        if (more) {
            #pragma unroll
            for (int i = 0; i < 4; i++) { fa[i] = pA[(c + 1) * 8 + i]; fb[i] = pB[(c + 1) * 8 + i]; }
        }

        // ---- MMA on stage c&1 ----
        {
            const uint32_t st = sb + (uint32_t)(c & 1) * STAGE_B;
            const uint32_t Ah = st, Bh = st + TILE_B;
            #pragma unroll
            for (int ks = 0; ks < 2; ks++) {
                uint32_t ah[16], bh[8];
                #pragma unroll
                for (int i = 0; i < 4; i++)
                    ldsm4(ah + 4 * i, Ah + a_off + i * (16 * TSTRIDE) + ks * 32);
                #pragma unroll
                for (int j = 0; j < 2; j++)
                    ldsm4(bh + 4 * j, Bh + b_off + j * (16 * TSTRIDE) + ks * 32);
                #pragma unroll
                for (int i = 0; i < 4; i++) {
                    #pragma unroll
                    for (int jn = 0; jn < 4; jn++) {
                        const uint32_t* bp = bh + (jn >> 1) * 4 + (jn & 1) * 2;
                        mma_fp16(acc[i][jn], ah + 4 * i, bp);
                    }
                }
            }
        }
        __syncthreads();

        if (more) {
            const uint32_t st = sb + (uint32_t)((c + 1) & 1) * STAGE_B;
            uint32_t h[8];
            #pragma unroll
            for (int i = 0; i < 4; i++) { h[2*i] = pack_h2(fa[i].x, fa[i].y); h[2*i+1] = pack_h2(fa[i].z, fa[i].w); }
            STS128(h[0], h[1], h[2], h[3], st + sts_off);
            STS128(h[4], h[5], h[6], h[7], st + sts_off + 16);
            #pragma unroll
            for (int i = 0; i < 4; i++) { h[2*i] = pack_h2(fb[i].x, fb[i].y); h[2*i+1] = pack_h2(fb[i].z, fb[i].w); }
            STS128(h[0], h[1], h[2], h[3], st + TILE_B + sts_off);
            STS128(h[4], h[5], h[6], h[7], st + TILE_B + sts_off + 16);
            #pragma unroll
            for (int i = 0; i < 4; i++) pBz[(c + 1) * 8 + i] = z4;  // re-zero W chunk (read exactly once)
            __syncthreads();
        }
    }

    // ---- epilogue: write K-split partials ----
    float* po = g_part + (size_t)blockIdx.y * BATCH * OUT_F + n0;
    #pragma unroll
    for (int i = 0; i < 4; i++) {
        const int m = wm + i * 16 + (lane >> 2);
        #pragma unroll
        for (int jn = 0; jn < 4; jn++) {
            const int n = wn + jn * 8 + (lane & 3) * 2;
            float2 v0 = make_float2(acc[i][jn][0], acc[i][jn][1]);
            float2 v1 = make_float2(acc[i][jn][2], acc[i][jn][3]);
            *(float2*)(po + (size_t)m * OUT_F + n)       = v0;
            *(float2*)(po + (size_t)(m + 8) * OUT_F + n) = v1;
        }
    }
}

// ===================== kernel 3: reduce partials + bias -> out =====================
__global__ void k_reduce(const float* __restrict__ bias, float* __restrict__ out) {
    const int i = blockIdx.x * blockDim.x + threadIdx.x;   // float4 index over [128,4096]
    const size_t stride = (size_t)BATCH * OUT_F / 4;       // 131072
    const float4* p = (const float4*)g_part;
    float4 b  = ((const float4*)bias)[i & 1023];
    float4 v0 = p[i];
    float4 v1 = p[i + stride];
    float4 v2 = p[i + 2 * stride];
    float4 v3 = p[i + 3 * stride];
    float4 s;
    s.x = b.x + v0.x + v1.x + v2.x + v3.x;
    s.y = b.y + v0.y + v1.y + v2.y + v3.y;
    s.z = b.z + v0.z + v1.z + v2.z + v3.z;
    s.w = b.w + v0.w + v1.w + v2.w + v3.w;
    ((float4*)out)[i] = s;
}

// ===================== launch =====================
extern "C" void kernel_launch(void* const* d_in, const int* in_sizes, int n_in,
                              void* d_out, int out_size) {
    const float* inp    = (const float*)d_in[0];   // [B, IN_F]
    const float* w_vals = (const float*)d_in[1];   // [nnz]
    const int*   w_rows = (const int*)  d_in[2];   // [nnz]
    const int*   w_cols = (const int*)  d_in[3];   // [nnz]
    const float* bias   = (const float*)d_in[4];   // [OUT_F]
    float*       out    = (float*)d_out;           // [B, OUT_F]
    const int n = in_sizes[1];

    cudaFuncSetAttribute(k_gemm, cudaFuncAttributeMaxDynamicSharedMemorySize, SMEM_TOTAL);

    k_scatter<<<2048, 256>>>(w_rows, w_cols, w_vals, n);
    k_gemm<<<dim3(32, KSPLIT), 256, SMEM_TOTAL>>>(inp);
    k_reduce<<<(BATCH * OUT_F / 4) / 256, 256>>>(bias, out);
}

// round 7
// speedup vs baseline: 2.1484x; 1.0626x over previous
#include <cuda_runtime.h>
#include <cuda_fp16.h>
#include <cstdint>

#define IN_F   4096
#define OUT_F  4096
#define BATCH  128
#define KSPLIT 4
#define KC     (IN_F / KSPLIT)     // 1024 K per CTA
#define CK     32                  // K per chunk
#define NCHUNK (KC / CK)           // 32
#define TSTRIDE 80                 // smem row stride (bytes): 64B data + 16B pad (16B-divisible)
#define TILE_B  (128 * TSTRIDE)    // 10240 B per 128x32 fp16 tile
#define STAGE_B (2 * TILE_B)       // A + B tile
#define STAGES  4
#define SMEM_TOTAL (STAGES * STAGE_B)  // 81920 B

// ===================== device scratch =====================
__device__ __align__(16) __half g_Wh[(size_t)OUT_F * IN_F];            // 32 MB dense fp16 W (zero invariant)
__device__ __align__(16) __half g_Ah[(size_t)BATCH * IN_F];            // 1 MB fp16 A
__device__ __align__(16) float  g_part[(size_t)KSPLIT * BATCH * OUT_F]; // 8 MB K-split partials

// ===================== helpers =====================
__device__ __forceinline__ uint32_t smem_u32(const void* p) {
    uint32_t a;
    asm("{ .reg .u64 t; cvta.to.shared.u64 t, %1; cvt.u32.u64 %0, t; }" : "=r"(a) : "l"(p));
    return a;
}
__device__ __forceinline__ void ldsm4(uint32_t* r, uint32_t addr) {
    asm volatile("ldmatrix.sync.aligned.m8n8.x4.shared.b16 {%0,%1,%2,%3}, [%4];"
                 : "=r"(r[0]), "=r"(r[1]), "=r"(r[2]), "=r"(r[3]) : "r"(addr));
}
__device__ __forceinline__ void mma_fp16(float* d, const uint32_t* a, const uint32_t* b) {
    asm volatile(
        "mma.sync.aligned.m16n8k16.row.col.f32.f16.f16.f32 "
        "{%0,%1,%2,%3}, {%4,%5,%6,%7}, {%8,%9}, {%0,%1,%2,%3};"
        : "+f"(d[0]), "+f"(d[1]), "+f"(d[2]), "+f"(d[3])
        : "r"(a[0]), "r"(a[1]), "r"(a[2]), "r"(a[3]), "r"(b[0]), "r"(b[1]));
}
__device__ __forceinline__ void cp_async16(uint32_t dst, const void* src) {
    asm volatile("cp.async.cg.shared.global [%0], [%1], 16;" :: "r"(dst), "l"(src) : "memory");
}
#define CP_COMMIT() asm volatile("cp.async.commit_group;" ::: "memory")
#define CP_WAIT(n)  asm volatile("cp.async.wait_group %0;" :: "n"(n) : "memory")

// ===================== kernel 1: convert A fp32 -> fp16 =====================
__global__ void k_convertA(const float* __restrict__ inp) {
    int i = blockIdx.x * blockDim.x + threadIdx.x;   // over (128*4096)/4 = 131072
    float4 v = ((const float4*)inp)[i];
    __half2 a = __floats2half2_rn(v.x, v.y);
    __half2 b = __floats2half2_rn(v.z, v.w);
    uint2 u;
    u.x = *reinterpret_cast<uint32_t*>(&a);
    u.y = *reinterpret_cast<uint32_t*>(&b);
    ((uint2*)g_Ah)[i] = u;
}

// ===================== kernel 2: scatter-add COO -> dense fp16 W =====================
__global__ void k_scatter(const int* __restrict__ rows, const int* __restrict__ cols,
                          const float* __restrict__ vals, int n) {
    int stride = gridDim.x * blockDim.x;
    for (int i = blockIdx.x * blockDim.x + threadIdx.x; i < n; i += stride)
        atomicAdd(&g_Wh[(size_t)rows[i] * IN_F + cols[i]], __float2half(vals[i]));
}

// ===================== kernel 3: fp16 GEMM, cp.async 4-stage pipeline =====================
// grid (32 n-tiles, 4 k-splits), 256 threads. Partials to g_part; W re-zero fused.
__global__ void __launch_bounds__(256, 1) k_gemm() {
    extern __shared__ char smem[];
    const uint32_t sb = smem_u32(smem);

    const int tid  = threadIdx.x;
    const int wid  = tid >> 5;
    const int lane = tid & 31;
    const int n0   = blockIdx.x * 128;
    const int kbase = blockIdx.y * KC;

    const int wm = (wid >> 2) * 64;   // warp m offset (0 / 64)
    const int wn = (wid & 3) * 32;    // warp n offset (0/32/64/96)

    float acc[4][4][4];
    #pragma unroll
    for (int i = 0; i < 4; i++)
        #pragma unroll
        for (int j = 0; j < 4; j++)
            #pragma unroll
            for (int c = 0; c < 4; c++) acc[i][j][c] = 0.f;

    // per-thread load mapping: 2 threads per row, 32B (16 halves) each
    const int r = tid >> 1;
    const int q = tid & 1;
    const __half* gA = g_Ah + (size_t)r * IN_F + kbase + q * 16;
    const __half* gB = g_Wh + (size_t)(n0 + r) * IN_F + kbase + q * 16;
    const uint32_t sts_off = (uint32_t)r * TSTRIDE + q * 32;

    // ---- prologue: issue chunks 0..STAGES-2 ----
    #pragma unroll
    for (int s = 0; s < STAGES - 1; s++) {
        const uint32_t st = sb + (uint32_t)s * STAGE_B;
        cp_async16(st + sts_off,               gA + s * CK);
        cp_async16(st + sts_off + 16,          gA + s * CK + 8);
        cp_async16(st + TILE_B + sts_off,      gB + s * CK);
        cp_async16(st + TILE_B + sts_off + 16, gB + s * CK + 8);
        CP_COMMIT();
    }

    // ldmatrix per-lane offsets (validated layout)
    const uint32_t a_off = (uint32_t)(wm + (lane & 15)) * TSTRIDE + (lane >> 4) * 16;
    const uint32_t b_off = (uint32_t)(wn + (lane & 7) + ((lane >> 4) & 1) * 8) * TSTRIDE
                         + ((lane >> 3) & 1) * 16;

    const uint4 z4 = make_uint4(0u, 0u, 0u, 0u);

    #pragma unroll 1
    for (int c = 0; c < NCHUNK; c++) {
        // wait for chunk c (own cp.asyncs done; <= STAGES-2 newer groups pending)
        CP_WAIT(STAGES - 2);
        // re-zero the W bytes this thread just loaded (own-thread ordering suffices)
        *(uint4*)(gB + c * CK)     = z4;
        *(uint4*)(gB + c * CK + 8) = z4;
        __syncthreads();   // all warps have finished MMA on stage (c-1)&3 == (c+3)&3

        // issue chunk c+STAGES-1 into the stage just vacated
        if (c + STAGES - 1 < NCHUNK) {
            const int cn = c + STAGES - 1;
            const uint32_t st = sb + (uint32_t)(cn & (STAGES - 1)) * STAGE_B;
            cp_async16(st + sts_off,               gA + cn * CK);
            cp_async16(st + sts_off + 16,          gA + cn * CK + 8);
            cp_async16(st + TILE_B + sts_off,      gB + cn * CK);
            cp_async16(st + TILE_B + sts_off + 16, gB + cn * CK + 8);
        }
        CP_COMMIT();   // unconditional: keeps group counting uniform

        // ---- MMA on stage c ----
        const uint32_t st = sb + (uint32_t)(c & (STAGES - 1)) * STAGE_B;
        const uint32_t At = st, Bt = st + TILE_B;
        #pragma unroll
        for (int ks = 0; ks < 2; ks++) {
            uint32_t ah[16], bh[8];
            #pragma unroll
            for (int i = 0; i < 4; i++)
                ldsm4(ah + 4 * i, At + a_off + i * (16 * TSTRIDE) + ks * 32);
            #pragma unroll
            for (int j = 0; j < 2; j++)
                ldsm4(bh + 4 * j, Bt + b_off + j * (16 * TSTRIDE) + ks * 32);
            #pragma unroll
            for (int i = 0; i < 4; i++) {
                #pragma unroll
                for (int jn = 0; jn < 4; jn++) {
                    const uint32_t* bp = bh + (jn >> 1) * 4 + (jn & 1) * 2;
                    mma_fp16(acc[i][jn], ah + 4 * i, bp);
                }
            }
        }
    }

    // ---- epilogue: write K-split partials ----
    float* po = g_part + (size_t)blockIdx.y * BATCH * OUT_F + n0;
    #pragma unroll
    for (int i = 0; i < 4; i++) {
        const int m = wm + i * 16 + (lane >> 2);
        #pragma unroll
        for (int jn = 0; jn < 4; jn++) {
            const int n = wn + jn * 8 + (lane & 3) * 2;
            float2 v0 = make_float2(acc[i][jn][0], acc[i][jn][1]);
            float2 v1 = make_float2(acc[i][jn][2], acc[i][jn][3]);
            *(float2*)(po + (size_t)m * OUT_F + n)       = v0;
            *(float2*)(po + (size_t)(m + 8) * OUT_F + n) = v1;
        }
    }
}

// ===================== kernel 4: reduce partials + bias -> out =====================
__global__ void k_reduce(const float* __restrict__ bias, float* __restrict__ out) {
    const int i = blockIdx.x * blockDim.x + threadIdx.x;   // float4 index over [128,4096]
    const size_t stride = (size_t)BATCH * OUT_F / 4;
    const float4* p = (const float4*)g_part;
    float4 b  = ((const float4*)bias)[i & 1023];
    float4 v0 = p[i];
    float4 v1 = p[i + stride];
    float4 v2 = p[i + 2 * stride];
    float4 v3 = p[i + 3 * stride];
    float4 s;
    s.x = b.x + v0.x + v1.x + v2.x + v3.x;
    s.y = b.y + v0.y + v1.y + v2.y + v3.y;
    s.z = b.z + v0.z + v1.z + v2.z + v3.z;
    s.w = b.w + v0.w + v1.w + v2.w + v3.w;
    ((float4*)out)[i] = s;
}

// ===================== launch =====================
extern "C" void kernel_launch(void* const* d_in, const int* in_sizes, int n_in,
                              void* d_out, int out_size) {
    const float* inp    = (const float*)d_in[0];   // [B, IN_F]
    const float* w_vals = (const float*)d_in[1];   // [nnz]
    const int*   w_rows = (const int*)  d_in[2];   // [nnz]
    const int*   w_cols = (const int*)  d_in[3];   // [nnz]
    const float* bias   = (const float*)d_in[4];   // [OUT_F]
    float*       out    = (float*)d_out;           // [B, OUT_F]
    const int n = in_sizes[1];

    cudaFuncSetAttribute(k_gemm, cudaFuncAttributeMaxDynamicSharedMemorySize, SMEM_TOTAL);

    k_convertA<<<(BATCH * IN_F / 4) / 256, 256>>>(inp);
    k_scatter<<<2048, 256>>>(w_rows, w_cols, w_vals, n);
    k_gemm<<<dim3(32, KSPLIT), 256, SMEM_TOTAL>>>();
    k_reduce<<<(BATCH * OUT_F / 4) / 256, 256>>>(bias, out);
}